// round 17
// baseline (speedup 1.0000x reference)
#include <cuda_runtime.h>
#include <cuda_bf16.h>
#include <math.h>

#define Nn 100000
#define Ee 1600000
#define Gg 64

// ---------------- packed f32x2 helpers ----------------
#define PACK2(out, a, b) \
    asm("mov.b64 %0, {%1, %2};" : "=l"(out) : "f"(a), "f"(b))
#define FMA2(acc, a, b) \
    asm("fma.rn.f32x2 %0, %1, %2, %0;" : "+l"(acc) : "l"(a), "l"(b))

// ---------------- device scratch (static, no runtime allocation) ----------------
__device__ int   g_cnt[Nn];
__device__ float g_dis[Nn];
__device__ float g_bufA[Nn * 64];       // gemm outputs (dis-prescaled hws)
__device__ float g_bufB[Nn * 64];       // epi outputs (pre-BN activations)
__device__ float g_bufC[Nn * 64];       // scatter accumulators (memset to 0)
__device__ float g_stats[3 * 128];      // per layer: [0..H) sum, [H..2H) sumsq
__device__ float g_pool[Gg * 33];       // per graph: sum[16], max[16], count

// ---------------- prefix kernels -------------------------------------------------
__global__ void k_zero() {
    int i = blockIdx.x * 256 + threadIdx.x;
    if (i < Nn) g_cnt[i] = 0;
    if (i < 3 * 128) g_stats[i] = 0.f;
}
__global__ void k_hist(const int* __restrict__ dst) {
    int e = blockIdx.x * 256 + threadIdx.x;
    if (e < Ee) atomicAdd(&g_cnt[dst[e]], 1);
}
__global__ void k_dis() {
    int i = blockIdx.x * 256 + threadIdx.x;
    if (i < Nn) g_dis[i] = rsqrtf((float)(g_cnt[i] + 1));
}

// ---------------- GEMM (exact round-5 body) --------------------------------------
template <int K, int H, bool NORM>
__global__ void __launch_bounds__(128, 4) k_gemm(const float* __restrict__ h,
                                                 const float* __restrict__ W,
                                                 const float* __restrict__ stats,
                                                 const float* __restrict__ gamma,
                                                 const float* __restrict__ beta,
                                                 float* __restrict__ out) {
    constexpr int C = H / 4;
    __shared__ float Wsm[16 * H];
    __shared__ float xt[16][128];
    __shared__ float nsc[K], nsh[K];
    const int tid = threadIdx.x;
    const int base = blockIdx.x * 128;
    const int n0 = (tid & 31) * 4;
    const int cg = tid >> 5;
    const int cbase = cg * C;

    if (NORM) {
        for (int c = tid; c < K; c += 128) {
            float m = stats[c] * (1.0f / Nn);
            float var = stats[K + c] * (1.0f / Nn) - m * m;
            float rstd = rsqrtf(var + 1e-5f);
            float sc = rstd * gamma[c];
            nsc[c] = sc;
            nsh[c] = beta[c] - m * sc;
        }
        __syncthreads();
    }

    unsigned long long acc2[4][C / 2];
#pragma unroll
    for (int t = 0; t < 4; t++)
#pragma unroll
        for (int j = 0; j < C / 2; j++) acc2[t][j] = 0ull;

    const int myrow = base + tid;

    for (int kc = 0; kc < K; kc += 16) {
        {
            const float4* Wg = reinterpret_cast<const float4*>(W + kc * H);
            float4* Ws = reinterpret_cast<float4*>(Wsm);
#pragma unroll
            for (int i = tid; i < 16 * H / 4; i += 128) Ws[i] = Wg[i];
        }
#pragma unroll
        for (int q = 0; q < 4; q++) {
            float4 v = make_float4(0.f, 0.f, 0.f, 0.f);
            if (myrow < Nn)
                v = *reinterpret_cast<const float4*>(h + (size_t)myrow * K + kc + q * 4);
            if (NORM) {
                int cb = kc + q * 4;
                v.x = v.x * nsc[cb + 0] + nsh[cb + 0]; v.x = v.x > 0.f ? v.x : 0.1f * v.x;
                v.y = v.y * nsc[cb + 1] + nsh[cb + 1]; v.y = v.y > 0.f ? v.y : 0.1f * v.y;
                v.z = v.z * nsc[cb + 2] + nsh[cb + 2]; v.z = v.z > 0.f ? v.z : 0.1f * v.z;
                v.w = v.w * nsc[cb + 3] + nsh[cb + 3]; v.w = v.w > 0.f ? v.w : 0.1f * v.w;
            }
            xt[q * 4 + 0][tid] = v.x;
            xt[q * 4 + 1][tid] = v.y;
            xt[q * 4 + 2][tid] = v.z;
            xt[q * 4 + 3][tid] = v.w;
        }
        __syncthreads();
#pragma unroll
        for (int kk = 0; kk < 16; kk++) {
            float4 xv = *reinterpret_cast<const float4*>(&xt[kk][n0]);
            unsigned long long x0, x1, x2, x3;
            PACK2(x0, xv.x, xv.x);
            PACK2(x1, xv.y, xv.y);
            PACK2(x2, xv.z, xv.z);
            PACK2(x3, xv.w, xv.w);
            const ulonglong2* w2 =
                reinterpret_cast<const ulonglong2*>(&Wsm[kk * H + cbase]);
#pragma unroll
            for (int j = 0; j < C / 4; j++) {
                ulonglong2 w = w2[j];
                FMA2(acc2[0][2 * j + 0], x0, w.x);
                FMA2(acc2[0][2 * j + 1], x0, w.y);
                FMA2(acc2[1][2 * j + 0], x1, w.x);
                FMA2(acc2[1][2 * j + 1], x1, w.y);
                FMA2(acc2[2][2 * j + 0], x2, w.x);
                FMA2(acc2[2][2 * j + 1], x2, w.y);
                FMA2(acc2[3][2 * j + 0], x3, w.x);
                FMA2(acc2[3][2 * j + 1], x3, w.y);
            }
        }
        __syncthreads();
    }

#pragma unroll
    for (int t = 0; t < 4; t++) {
        int node = base + n0 + t;
        if (node < Nn) {
            float dn = g_dis[node];
            const float* a = reinterpret_cast<const float*>(acc2[t]);
            float* o = out + (size_t)node * H + cbase;
#pragma unroll
            for (int j = 0; j < C / 4; j++) {
                float4 r;
                r.x = a[4 * j + 0] * dn;
                r.y = a[4 * j + 1] * dn;
                r.z = a[4 * j + 2] * dn;
                r.w = a[4 * j + 3] * dn;
                *reinterpret_cast<float4*>(o + 4 * j) = r;
            }
        }
    }
}

// ---------------- scatter-add: acc[dst] += hws[src], edge-parallel ---------------
// Warp handles 4 edges per iteration: all src/dst + row loads issued before any
// atomic; RED.ADD.F32 has no return latency -> no exposed chains.
template <int H>
__global__ void __launch_bounds__(256) k_scatter(const float* __restrict__ hws,
                                                 const int* __restrict__ src,
                                                 const int* __restrict__ dst,
                                                 float* __restrict__ acc) {
    constexpr int NCH = (H >= 32) ? H / 32 : 1;
    const int lane = threadIdx.x & 31;
    const int warp = (blockIdx.x * blockDim.x + threadIdx.x) >> 5;
    const int nwarps = (gridDim.x * blockDim.x) >> 5;
    const bool act = (H >= 32) || (lane < H);

    const int quads = Ee / 4;   // Ee divisible by 4
    for (int q = warp; q < quads; q += nwarps) {
        const int e = 4 * q;
        int s0 = src[e + 0], s1 = src[e + 1], s2 = src[e + 2], s3 = src[e + 3];
        int d0 = dst[e + 0], d1 = dst[e + 1], d2 = dst[e + 2], d3 = dst[e + 3];
        if (act) {
            float v[4][NCH];
#pragma unroll
            for (int j = 0; j < NCH; j++) {
                int c = lane + 32 * j;
                v[0][j] = hws[(size_t)s0 * H + c];
                v[1][j] = hws[(size_t)s1 * H + c];
                v[2][j] = hws[(size_t)s2 * H + c];
                v[3][j] = hws[(size_t)s3 * H + c];
            }
#pragma unroll
            for (int j = 0; j < NCH; j++) {
                int c = lane + 32 * j;
                atomicAdd(&acc[(size_t)d0 * H + c], v[0][j]);
                atomicAdd(&acc[(size_t)d1 * H + c], v[1][j]);
                atomicAdd(&acc[(size_t)d2 * H + c], v[2][j]);
                atomicAdd(&acc[(size_t)d3 * H + c], v[3][j]);
            }
        }
    }
}

// ---------------- epilogue: pre = dis*(acc + self) + b, fused BN stats -----------
template <int H>
__global__ void __launch_bounds__(256) k_epi(const float* __restrict__ acc,
                                             const float* __restrict__ self,
                                             const float* __restrict__ b,
                                             float* __restrict__ pre,
                                             float* __restrict__ stats) {
    constexpr int NCH = (H >= 32) ? H / 32 : 1;
    const int lane = threadIdx.x & 31;
    const int warp = (blockIdx.x * blockDim.x + threadIdx.x) >> 5;
    const int nwarps = (gridDim.x * blockDim.x) >> 5;
    const bool act = (H >= 32) || (lane < H);

    float s_sum[NCH], s_sq[NCH];
#pragma unroll
    for (int j = 0; j < NCH; j++) { s_sum[j] = 0.f; s_sq[j] = 0.f; }

    for (int node = warp; node < Nn; node += nwarps) {
        if (act) {
            float dn = g_dis[node];
#pragma unroll
            for (int j = 0; j < NCH; j++) {
                int c = lane + 32 * j;
                float v = dn * (acc[(size_t)node * H + c] + self[(size_t)node * H + c]) + b[c];
                pre[(size_t)node * H + c] = v;
                s_sum[j] += v;
                s_sq[j] += v * v;
            }
        }
    }
    if (act) {
#pragma unroll
        for (int j = 0; j < NCH; j++) {
            int c = lane + 32 * j;
            atomicAdd(&stats[c], s_sum[j]);
            atomicAdd(&stats[H + c], s_sq[j]);
        }
    }
}

// ---------------- pooling (exact round-5) ----------------------------------------
__device__ __forceinline__ int lower_bound_batch(const int* __restrict__ batch, int g) {
    int lo = 0, hi = Nn;
    while (lo < hi) {
        int m = (lo + hi) >> 1;
        if (batch[m] < g) lo = m + 1; else hi = m;
    }
    return lo;
}

__global__ void k_pool(const float* __restrict__ x3, const int* __restrict__ batch,
                       const float* __restrict__ stats,
                       const float* __restrict__ gamma, const float* __restrict__ beta) {
    __shared__ int ss, se;
    __shared__ float ssum[256], smax[256];
    int g = blockIdx.x, t = threadIdx.x;
    if (t == 0) { ss = lower_bound_batch(batch, g); se = lower_bound_batch(batch, g + 1); }
    __syncthreads();
    int s = ss, e = se;
    int c = t & 15;
    float m = stats[c] * (1.0f / Nn);
    float var = stats[16 + c] * (1.0f / Nn) - m * m;
    float rstd = rsqrtf(var + 1e-5f);
    float sc = rstd * gamma[c];
    float sh = beta[c] - m * sc;

    float sum = 0.f, mx = -3.402823466e+38f;
    for (int r = s + (t >> 4); r < e; r += 16) {
        float v = x3[(size_t)r * 16 + c] * sc + sh;
        v = v > 0.f ? v : 0.1f * v;
        sum += v;
        mx = fmaxf(mx, v);
    }
    ssum[t] = sum; smax[t] = mx;
    __syncthreads();
    for (int off = 128; off >= 16; off >>= 1) {
        if (t < off) { ssum[t] += ssum[t + off]; smax[t] = fmaxf(smax[t], smax[t + off]); }
        __syncthreads();
    }
    if (t < 16) { g_pool[g * 33 + t] = ssum[t]; g_pool[g * 33 + 16 + t] = smax[t]; }
    if (t == 0) g_pool[g * 33 + 32] = (float)(e - s);
}

// ---------------- head (exact round-5) --------------------------------------------
__global__ void k_head(const float* __restrict__ attn_w, const float* __restrict__ attn_b,
                       const float* __restrict__ fc1_w, const float* __restrict__ fc1_b,
                       const float* __restrict__ fc2_w, const float* __restrict__ fc2_b,
                       const float* __restrict__ out_w, const float* __restrict__ out_b,
                       float* __restrict__ out) {
    int g = threadIdx.x;
    if (g >= Gg) return;
    float sm[16], mx[16], mean[16];
    float cnt = g_pool[g * 33 + 32];
    float inv = 1.0f / fmaxf(cnt, 1.0f);
#pragma unroll
    for (int k = 0; k < 16; k++) {
        sm[k] = g_pool[g * 33 + k];
        mx[k] = g_pool[g * 33 + 16 + k];
        mean[k] = sm[k] * inv;
    }
    float z[3];
#pragma unroll
    for (int j = 0; j < 3; j++) z[j] = attn_b[j];
#pragma unroll
    for (int k = 0; k < 16; k++) {
#pragma unroll
        for (int j = 0; j < 3; j++) {
            z[j] += mean[k] * attn_w[k * 3 + j]
                  + mx[k]   * attn_w[(16 + k) * 3 + j]
                  + sm[k]   * attn_w[(32 + k) * 3 + j];
        }
    }
    float zm = fmaxf(z[0], fmaxf(z[1], z[2]));
    float e0 = expf(z[0] - zm), e1 = expf(z[1] - zm), e2 = expf(z[2] - zm);
    float is = 1.f / (e0 + e1 + e2);
    float a0 = e0 * is, a1 = e1 * is, a2 = e2 * is;
    float xg[16];
#pragma unroll
    for (int k = 0; k < 16; k++) xg[k] = a0 * mean[k] + a1 * mx[k] + a2 * sm[k];
    float y1[16];
#pragma unroll
    for (int j = 0; j < 16; j++) {
        float acc = fc1_b[j];
#pragma unroll
        for (int k = 0; k < 16; k++) acc += xg[k] * fc1_w[k * 16 + j];
        y1[j] = acc > 0.f ? acc : 0.1f * acc;
    }
    float y2[8];
#pragma unroll
    for (int j = 0; j < 8; j++) {
        float acc = fc2_b[j];
#pragma unroll
        for (int k = 0; k < 16; k++) acc += y1[k] * fc2_w[k * 8 + j];
        y2[j] = acc > 0.f ? acc : 0.1f * acc;
    }
    float o = out_b[0];
#pragma unroll
    for (int k = 0; k < 8; k++) o += y2[k] * out_w[k];
    out[g] = 1.f / (1.f + expf(-o));
}

// ---------------- host launch -----------------------------------------------------
extern "C" void kernel_launch(void* const* d_in, const int* in_sizes, int n_in,
                              void* d_out, int out_size) {
    const float* x      = (const float*)d_in[0];
    const float* W1     = (const float*)d_in[1];
    const float* b1     = (const float*)d_in[2];
    const float* W2     = (const float*)d_in[3];
    const float* b2     = (const float*)d_in[4];
    const float* W3     = (const float*)d_in[5];
    const float* b3     = (const float*)d_in[6];
    const float* g1     = (const float*)d_in[7];
    const float* be1    = (const float*)d_in[8];
    const float* g2     = (const float*)d_in[9];
    const float* be2    = (const float*)d_in[10];
    const float* g3     = (const float*)d_in[11];
    const float* be3    = (const float*)d_in[12];
    const float* attn_w = (const float*)d_in[13];
    const float* attn_b = (const float*)d_in[14];
    const float* fc1_w  = (const float*)d_in[15];
    const float* fc1_b  = (const float*)d_in[16];
    const float* fc2_w  = (const float*)d_in[17];
    const float* fc2_b  = (const float*)d_in[18];
    const float* out_w  = (const float*)d_in[19];
    const float* out_b  = (const float*)d_in[20];
    const int*   ei     = (const int*)d_in[21];
    const int*   batch  = (const int*)d_in[22];

    const int* src = ei;
    const int* dst = ei + Ee;
    float* out = (float*)d_out;

    void *pA = nullptr, *pB = nullptr, *pC = nullptr, *pS = nullptr;
    cudaGetSymbolAddress(&pA, g_bufA);
    cudaGetSymbolAddress(&pB, g_bufB);
    cudaGetSymbolAddress(&pC, g_bufC);
    cudaGetSymbolAddress(&pS, g_stats);
    float* bufA = (float*)pA;
    float* bufB = (float*)pB;
    float* bufC = (float*)pC;
    float* st0 = (float*)pS;
    float* st1 = st0 + 128;
    float* st2 = st0 + 256;

    static cudaStream_t sB = nullptr;
    static cudaEvent_t evFork = nullptr, evJoin = nullptr;
    if (sB == nullptr) {
        cudaStreamCreateWithFlags(&sB, cudaStreamNonBlocking);
        cudaEventCreateWithFlags(&evFork, cudaEventDisableTiming);
        cudaEventCreateWithFlags(&evJoin, cudaEventDisableTiming);
    }

    const int gemm_grid = (Nn + 127) / 128;   // 782
    const int work_grid = 1184;               // 148 SMs * 8 blocks

    // ---- prefix: degree + dis ----
    k_zero<<<(Nn + 255) / 256, 256>>>();
    k_hist<<<(Ee + 255) / 256, 256>>>(dst);
    k_dis<<<(Nn + 255) / 256, 256>>>();
    cudaEventRecord(evFork, 0);

    // ---- branch B: GEMM1 (needs only dis) ----
    cudaStreamWaitEvent(sB, evFork, 0);
    k_gemm<128, 64, false><<<gemm_grid, 128, 0, sB>>>(x, W1, nullptr, nullptr, nullptr, bufA);
    cudaEventRecord(evJoin, sB);

    // ---- main: zero layer-1 accumulator (overlaps GEMM1) ----
    cudaMemsetAsync(bufC, 0, (size_t)Nn * 64 * sizeof(float), 0);

    // ---- layer 1: scatter + epilogue ----
    cudaStreamWaitEvent(0, evJoin, 0);
    k_scatter<64><<<work_grid, 256>>>(bufA, src, dst, bufC);
    k_epi<64><<<work_grid, 256>>>(bufC, bufA, b1, bufB, st0);

    // ---- layer 2 ----
    k_gemm<64, 32, true><<<gemm_grid, 128>>>(bufB, W2, st0, g1, be1, bufA);
    cudaMemsetAsync(bufC, 0, (size_t)Nn * 32 * sizeof(float), 0);
    k_scatter<32><<<work_grid, 256>>>(bufA, src, dst, bufC);
    k_epi<32><<<work_grid, 256>>>(bufC, bufA, b2, bufB, st1);

    // ---- layer 3 ----
    k_gemm<32, 16, true><<<gemm_grid, 128>>>(bufB, W3, st1, g2, be2, bufA);
    cudaMemsetAsync(bufC, 0, (size_t)Nn * 16 * sizeof(float), 0);
    k_scatter<16><<<work_grid, 256>>>(bufA, src, dst, bufC);
    k_epi<16><<<work_grid, 256>>>(bufC, bufA, b3, bufB, st2);

    // ---- pool + head ----
    k_pool<<<Gg, 256>>>(bufB, batch, st2, g3, be3);
    k_head<<<1, 64>>>(attn_w, attn_b, fc1_w, fc1_b, fc2_w, fc2_b, out_w, out_b, out);
}